// round 8
// baseline (speedup 1.0000x reference)
#include <cuda_runtime.h>

#define B_  4
#define O_  32
#define C_  32
#define HW_ 32
#define P_  5
#define T_  (C_ * 9)      // 288 taps per output channel
#define EPSF 1e-6f
#define TS_ 36            // x-tile row stride (floats), rows 16B-aligned

// fused multiply-add with saturate-to-[0,1] (proven exact vs reference in R3)
__device__ __forceinline__ float fma_sat(float a, float b, float c) {
    float d;
    asm("fma.rn.sat.f32 %0, %1, %2, %3;" : "=f"(d) : "f"(a), "f"(b), "f"(c));
    return d;
}
// acc += w via FFMA with IMMEDIATE multiplier 1.0 (rt_SMSP=1 imm-FFMA form)
__device__ __forceinline__ float fma_acc1(float w, float acc) {
    float d;
    asm("fma.rn.f32 %0, %1, 0f3F800000, %2;" : "=f"(d) : "f"(w), "f"(acc));
    return d;
}

// ---------------------------------------------------------------------------
// Fused kernel. Grid: 512 = (b, o, 8-row quarter) -> single wave (<=592 slots).
// Block: 256 = 8 warps = 4 channel-groups x 2 row-groups.
// Phase 0: sort this o's 288 (pos,val)[5] tables (Bose-Nelson 9 CE) ->
//   per tap 4 float4 (64B): segs 0,1 in sat form {inv,nq,dv,-};
//   segs 2,3 in dv-scaled clamp form {inv*dv, nq*dv, min(0,dv), max(0,dv)}.
//   f(x) = v0 + sum_k dv_k*sat((x-p_k)*inv_k); form B computes dv*sat(u) as
//   clamp(dv*u, min(0,dv), max(0,dv)) -- identical bounded numerics, but the
//   clamp runs on the ALU pipe (FMNMX) and the accumulate on rt-1 imm-FFMA,
//   balancing the two rt-2 pipes instead of piling everything on fma.
// Phase 1: warp (cg=w&3, rg=w>>2): channels 8cg..8cg+7, 4-row group rg,
//   4 px/thread. x per-warp double-buffered 6x36 tile. Tables via uniform
//   LDS.128 broadcast (4 per tap).
// Phase 2: 4-way float4 smem reduction + bias, STG.128.
// ---------------------------------------------------------------------------
__global__ __launch_bounds__(256, 4) void pc_fused(const float* __restrict__ x,
                                                   const float* __restrict__ pos,
                                                   const float* __restrict__ val,
                                                   float* __restrict__ out) {
    const int blk = blockIdx.x;
    const int quarter = blk & 3;           // 8-row strip
    const int o = (blk >> 2) & 31;
    const int b = blk >> 7;
    const int y0 = quarter * 8;

    __shared__ float4 s_tab[T_ * 4];        // 18432 B
    __shared__ float  s_v0[T_];             // 1152 B
    __shared__ float  s_x[16][6 * TS_];     // 2 tiles/warp, 13824 B
    __shared__ float4 s_red[4][64];         // 4096 B
    __shared__ float  s_bias;

    const int tid = threadIdx.x;

    // ---- Phase 0: build mixed-form coefficient tables for this o ----
    const float* pbase = pos + o * (T_ * P_);
    const float* vbase = val + o * (T_ * P_);
#pragma unroll
    for (int rep = 0; rep < 2; rep++) {
        int ot = tid + rep * 256;
        if (ot < T_) {
            float p[P_], v[P_];
#pragma unroll
            for (int k = 0; k < P_; k++) { p[k] = pbase[ot * P_ + k]; v[k] = vbase[ot * P_ + k]; }
#define CE(a, bb) do { if (p[a] > p[bb]) { float t0 = p[a]; p[a] = p[bb]; p[bb] = t0; \
                                           float t1 = v[a]; v[a] = v[bb]; v[bb] = t1; } } while (0)
            CE(0,1); CE(3,4); CE(2,4); CE(2,3); CE(1,4); CE(0,3); CE(0,2); CE(1,3); CE(1,2);
#undef CE
            float inv[4], nq[4], dv[4];
#pragma unroll
            for (int k = 0; k < 4; k++) {
                float den = p[k + 1] - p[k] + EPSF;
                inv[k] = 1.0f / den;
                nq[k]  = -p[k] * inv[k];
                dv[k]  = v[k + 1] - v[k];
            }
            // segs 0,1: sat form (fma-pipe)
            s_tab[ot * 4 + 0] = make_float4(inv[0], nq[0], dv[0], 0.0f);
            s_tab[ot * 4 + 1] = make_float4(inv[1], nq[1], dv[1], 0.0f);
            // segs 2,3: dv-scaled clamp form (alu-pipe clamps)
#pragma unroll
            for (int k = 2; k < 4; k++) {
                float lo = fminf(0.0f, dv[k]);
                float hi = fmaxf(0.0f, dv[k]);
                s_tab[ot * 4 + k] = make_float4(inv[k] * dv[k], nq[k] * dv[k], lo, hi);
            }
            s_v0[ot] = v[0];
        }
    }
    __syncthreads();

    if (tid < 32) {        // bias = sum_t v0
        float s = 0.0f;
#pragma unroll
        for (int k = 0; k < 9; k++) s += s_v0[tid + k * 32];
#pragma unroll
        for (int off = 16; off > 0; off >>= 1) s += __shfl_down_sync(0xffffffffu, s, off);
        if (tid == 0) s_bias = s;
    }
    __syncthreads();

    // ---- Phase 1 ----
    const int warp = tid >> 5;
    const int lane = tid & 31;
    const int cg   = warp & 3;             // 0..3: 8-channel group
    const int rg   = warp >> 2;            // 0/1 : 4-row group within strip
    const int rl   = lane >> 3;            // 0..3: row within 4-row group
    const int xg   = (lane & 7) * 4;       // 0,4,...,28
    const int rowbase = y0 + rg * 4 - 1;

    int  rowoff[6];
    bool okA[6], okB[6];
#pragma unroll
    for (int rr = 0; rr < 6; rr++) {
        int gy = rowbase + rr;
        bool rowok = (gy >= 0) && (gy < HW_);
        rowoff[rr] = gy * HW_;
        okA[rr] = rowok && (lane >= 1);
        okB[rr] = rowok && (lane == 0);
    }

    float acc0 = 0.0f, acc1 = 0.0f, acc2 = 0.0f, acc3 = 0.0f;

    const float* xb = x + b * (C_ * HW_ * HW_);
    const int cBase = cg * 8;
    const float* xc = xb + cBase * (HW_ * HW_);
    float* tA = s_x[warp * 2];
    float* tB = s_x[warp * 2 + 1];

#define FILL(T_PTR, XC) do {                                               \
    const float* xp_ = (XC);                                               \
    _Pragma("unroll")                                                      \
    for (int rr = 0; rr < 6; rr++) {                                       \
        float v_ = okA[rr] ? xp_[rowoff[rr] + lane - 1] : 0.0f;            \
        (T_PTR)[rr * TS_ + lane] = v_;                                     \
        if (lane < 2) {                                                    \
            float v2_ = okB[rr] ? xp_[rowoff[rr] + 31] : 0.0f;             \
            (T_PTR)[rr * TS_ + 32 + lane] = v2_;                           \
        }                                                                  \
    } } while (0)

// Form A (sat-fused, fma pipe only): acc += dv * sat(x*inv + nq)
#define SEGA(TQ) do {                                                      \
        float u0 = fma_sat(xv0, (TQ).x, (TQ).y);                           \
        float u1 = fma_sat(xv1, (TQ).x, (TQ).y);                           \
        float u2 = fma_sat(xv2, (TQ).x, (TQ).y);                           \
        float u3 = fma_sat(xv3, (TQ).x, (TQ).y);                           \
        acc0 = fmaf((TQ).z, u0, acc0);                                     \
        acc1 = fmaf((TQ).z, u1, acc1);                                     \
        acc2 = fmaf((TQ).z, u2, acc2);                                     \
        acc3 = fmaf((TQ).z, u3, acc3);                                     \
    } while (0)
// Form B (alu clamps + rt-1 imm accumulate):
//   w = clamp(x*invdv + nqdv, min(0,dv), max(0,dv)); acc += w
#define SEGB(TQ) do {                                                      \
        float u0 = fmaf(xv0, (TQ).x, (TQ).y);                              \
        float u1 = fmaf(xv1, (TQ).x, (TQ).y);                              \
        float u2 = fmaf(xv2, (TQ).x, (TQ).y);                              \
        float u3 = fmaf(xv3, (TQ).x, (TQ).y);                              \
        u0 = fminf(fmaxf(u0, (TQ).z), (TQ).w);                             \
        u1 = fminf(fmaxf(u1, (TQ).z), (TQ).w);                             \
        u2 = fminf(fmaxf(u2, (TQ).z), (TQ).w);                             \
        u3 = fminf(fmaxf(u3, (TQ).z), (TQ).w);                             \
        acc0 = fma_acc1(u0, acc0);                                         \
        acc1 = fma_acc1(u1, acc1);                                         \
        acc2 = fma_acc1(u2, acc2);                                         \
        acc3 = fma_acc1(u3, acc3);                                         \
    } while (0)

    FILL(tA, xc);                          // prefetch first channel

#pragma unroll 2
    for (int cc = 0; cc < 8; cc++) {
        float* cur = (cc & 1) ? tB : tA;
        float* nxt = (cc & 1) ? tA : tB;
        __syncwarp();

        // 3 rows x 6 cols neighborhood via LDS.128 + LDS.64
        float vreg[3][6];
#pragma unroll
        for (int ii = 0; ii < 3; ii++) {
            const float* rp = cur + (rl + ii) * TS_ + xg;
            float4 a = *reinterpret_cast<const float4*>(rp);
            float2 bb = *reinterpret_cast<const float2*>(rp + 4);
            vreg[ii][0] = a.x; vreg[ii][1] = a.y; vreg[ii][2] = a.z;
            vreg[ii][3] = a.w; vreg[ii][4] = bb.x; vreg[ii][5] = bb.y;
        }

        if (cc < 7) FILL(nxt, xc + (HW_ * HW_));   // overlap LDG with math
        xc += HW_ * HW_;

        const float4* tp = s_tab + (cBase + cc) * 36;
#pragma unroll
        for (int i = 0; i < 3; i++) {
#pragma unroll
            for (int j = 0; j < 3; j++) {
                const float4* t4 = tp + (i * 3 + j) * 4;
                float4 c0 = t4[0];         // uniform -> broadcast
                float4 c1 = t4[1];
                float4 c2 = t4[2];
                float4 c3 = t4[3];
                float xv0 = vreg[i][j + 0];
                float xv1 = vreg[i][j + 1];
                float xv2 = vreg[i][j + 2];
                float xv3 = vreg[i][j + 3];
                SEGA(c0);
                SEGB(c2);
                SEGA(c1);
                SEGB(c3);
            }
        }
    }
#undef SEGA
#undef SEGB
#undef FILL

    // ---- Phase 2: reduce across the 4 channel-groups ----
    const int g = rg * 32 + rl * 8 + (lane & 7);   // 0..63 pixel group
    s_red[cg][g] = make_float4(acc0, acc1, acc2, acc3);
    __syncthreads();

    if (tid < 64) {
        float bias = s_bias;
        float4 r0 = s_red[0][tid];
        float4 r1 = s_red[1][tid];
        float4 r2 = s_red[2][tid];
        float4 r3 = s_red[3][tid];
        float4 res;
        res.x = bias + (r0.x + r1.x) + (r2.x + r3.x);
        res.y = bias + (r0.y + r1.y) + (r2.y + r3.y);
        res.z = bias + (r0.z + r1.z) + (r2.z + r3.z);
        res.w = bias + (r0.w + r1.w) + (r2.w + r3.w);
        int row = tid >> 3;
        int col0 = (tid & 7) * 4;
        int oidx = ((b * O_ + o) * HW_ + y0 + row) * HW_ + col0;
        *reinterpret_cast<float4*>(out + oidx) = res;
    }
}

extern "C" void kernel_launch(void* const* d_in, const int* in_sizes, int n_in,
                              void* d_out, int out_size) {
    const float* x   = (const float*)d_in[0];
    const float* pos = (const float*)d_in[1];
    const float* val = (const float*)d_in[2];
    float* out = (float*)d_out;

    pc_fused<<<B_ * O_ * 4, 256>>>(x, pos, val, out);
}

// round 9
// speedup vs baseline: 1.1872x; 1.1872x over previous
#include <cuda_runtime.h>

#define B_  4
#define O_  32
#define C_  32
#define HW_ 32
#define P_  5
#define T_  (C_ * 9)      // 288 taps per output channel
#define EPSF 1e-6f
#define TS_ 36            // x-tile row stride (floats), rows 16B-aligned

// fused multiply-add with saturate-to-[0,1] — proven exact vs reference (R3)
__device__ __forceinline__ float fma_sat(float a, float b, float c) {
    float d;
    asm("fma.rn.sat.f32 %0, %1, %2, %3;" : "=f"(d) : "f"(a), "f"(b), "f"(c));
    return d;
}

// ---------------------------------------------------------------------------
// R3 math on the R7 load-balanced skeleton.
// Grid: 1024 = (b, o, 4-row strip of 8)  -> ~1% block-count skew across SMs
//   (vs 15% at 512 blocks with 4-resident-block placement).
// Block: 256 = 8 warps; warp w handles channels 4w..4w+3 over the full strip,
//   4 px/thread (rl = row, xg = 4-col group).
// Phase 0: sort this o's 288 (pos,val)[5] tables (Bose-Nelson 9 CE) ->
//   clamped-ramp coefficients: f(x) = v0 + sum_k dv_k * sat((x-p_k)*inv_k)
//   (identical numerics to the reference's eps-lerp + boundary clamps).
//   Per tap 3 float4: {inv0..3},{nq0..3},{dv0..3} -> 3 uniform LDS.128.
// Phase 1: per-warp double-buffered 6x36 x-tile (LDS.128+LDS.64 reads),
//   8 FFMA-class instr per px-tap (the minimum), all accumulator chains
//   8 instructions apart (>= FFMA latency).
// Phase 2: 8-way float4 smem reduction + bias, STG.128.
// ---------------------------------------------------------------------------
__global__ __launch_bounds__(256, 4) void pc_fused(const float* __restrict__ x,
                                                   const float* __restrict__ pos,
                                                   const float* __restrict__ val,
                                                   float* __restrict__ out) {
    const int blk = blockIdx.x;
    const int strip = blk & 7;             // 0..7 : 4-row strip
    const int o = (blk >> 3) & 31;
    const int b = blk >> 8;
    const int y0 = strip * 4;

    __shared__ float4 s_tab[T_ * 3];        // 13824 B
    __shared__ float  s_v0[T_];             // 1152 B
    __shared__ float  s_x[16][6 * TS_];     // 2 tiles/warp, 13824 B
    __shared__ float4 s_red[8][32];         // 4096 B
    __shared__ float  s_bias;

    const int tid = threadIdx.x;

    // ---- Phase 0: build coefficient tables for this o ----
    const float* pbase = pos + o * (T_ * P_);
    const float* vbase = val + o * (T_ * P_);
#pragma unroll
    for (int rep = 0; rep < 2; rep++) {
        int ot = tid + rep * 256;
        if (ot < T_) {
            float p[P_], v[P_];
#pragma unroll
            for (int k = 0; k < P_; k++) { p[k] = pbase[ot * P_ + k]; v[k] = vbase[ot * P_ + k]; }
#define CE(a, bb) do { if (p[a] > p[bb]) { float t0 = p[a]; p[a] = p[bb]; p[bb] = t0; \
                                           float t1 = v[a]; v[a] = v[bb]; v[bb] = t1; } } while (0)
            CE(0,1); CE(3,4); CE(2,4); CE(2,3); CE(1,4); CE(0,3); CE(0,2); CE(1,3); CE(1,2);
#undef CE
            float inv[4], nq[4], dv[4];
#pragma unroll
            for (int k = 0; k < 4; k++) {
                float den = p[k + 1] - p[k] + EPSF;
                inv[k] = 1.0f / den;
                nq[k]  = -p[k] * inv[k];
                dv[k]  = v[k + 1] - v[k];
            }
            s_tab[ot * 3 + 0] = make_float4(inv[0], inv[1], inv[2], inv[3]);
            s_tab[ot * 3 + 1] = make_float4(nq[0],  nq[1],  nq[2],  nq[3]);
            s_tab[ot * 3 + 2] = make_float4(dv[0],  dv[1],  dv[2],  dv[3]);
            s_v0[ot] = v[0];
        }
    }
    __syncthreads();

    if (tid < 32) {        // bias = sum_t v0
        float s = 0.0f;
#pragma unroll
        for (int k = 0; k < 9; k++) s += s_v0[tid + k * 32];
#pragma unroll
        for (int off = 16; off > 0; off >>= 1) s += __shfl_down_sync(0xffffffffu, s, off);
        if (tid == 0) s_bias = s;
    }
    __syncthreads();

    // ---- Phase 1 ----
    const int warp = tid >> 5;
    const int lane = tid & 31;
    const int rl   = lane >> 3;            // 0..3: row within strip
    const int xg   = (lane & 7) * 4;       // 0,4,...,28
    const int rowbase = y0 - 1;            // tile row 0 = global row y0-1

    int  rowoff[6];
    bool okA[6], okB[6];
#pragma unroll
    for (int rr = 0; rr < 6; rr++) {
        int gy = rowbase + rr;
        bool rowok = (gy >= 0) && (gy < HW_);
        rowoff[rr] = gy * HW_;
        okA[rr] = rowok && (lane >= 1);
        okB[rr] = rowok && (lane == 0);
    }

    float acc0 = 0.0f, acc1 = 0.0f, acc2 = 0.0f, acc3 = 0.0f;

    const float* xb = x + b * (C_ * HW_ * HW_);
    const int cBase = warp * 4;            // 4 channels per warp
    const float* xc = xb + cBase * (HW_ * HW_);
    float* tA = s_x[warp * 2];
    float* tB = s_x[warp * 2 + 1];

#define FILL(T_PTR, XC) do {                                               \
    const float* xp_ = (XC);                                               \
    _Pragma("unroll")                                                      \
    for (int rr = 0; rr < 6; rr++) {                                       \
        float v_ = okA[rr] ? xp_[rowoff[rr] + lane - 1] : 0.0f;            \
        (T_PTR)[rr * TS_ + lane] = v_;                                     \
        if (lane < 2) {                                                    \
            float v2_ = okB[rr] ? xp_[rowoff[rr] + 31] : 0.0f;             \
            (T_PTR)[rr * TS_ + 32 + lane] = v2_;                           \
        }                                                                  \
    } } while (0)

// One segment for all 4 pixels: FFMA.SAT + FFMA each (8 instr/px-tap total)
#define SEG(CI, CQ, CD) do {                                               \
        float u0 = fma_sat(xv0, (CI), (CQ));                               \
        float u1 = fma_sat(xv1, (CI), (CQ));                               \
        float u2 = fma_sat(xv2, (CI), (CQ));                               \
        float u3 = fma_sat(xv3, (CI), (CQ));                               \
        acc0 = fmaf(u0, (CD), acc0);                                       \
        acc1 = fmaf(u1, (CD), acc1);                                       \
        acc2 = fmaf(u2, (CD), acc2);                                       \
        acc3 = fmaf(u3, (CD), acc3);                                       \
    } while (0)

    FILL(tA, xc);                          // prefetch first channel

    for (int cc = 0; cc < 4; cc++) {
        float* cur = (cc & 1) ? tB : tA;
        float* nxt = (cc & 1) ? tA : tB;
        __syncwarp();

        // 3 rows x 6 cols neighborhood via LDS.128 + LDS.64
        float vreg[3][6];
#pragma unroll
        for (int ii = 0; ii < 3; ii++) {
            const float* rp = cur + (rl + ii) * TS_ + xg;
            float4 a = *reinterpret_cast<const float4*>(rp);
            float2 bb = *reinterpret_cast<const float2*>(rp + 4);
            vreg[ii][0] = a.x; vreg[ii][1] = a.y; vreg[ii][2] = a.z;
            vreg[ii][3] = a.w; vreg[ii][4] = bb.x; vreg[ii][5] = bb.y;
        }

        if (cc < 3) FILL(nxt, xc + (HW_ * HW_));   // overlap LDG with math
        xc += HW_ * HW_;

        const float4* tp = s_tab + (cBase + cc) * 27;
#pragma unroll
        for (int i = 0; i < 3; i++) {
#pragma unroll
            for (int j = 0; j < 3; j++) {
                float4 iv = tp[(i * 3 + j) * 3 + 0];   // uniform -> broadcast
                float4 nq = tp[(i * 3 + j) * 3 + 1];
                float4 dv = tp[(i * 3 + j) * 3 + 2];
                float xv0 = vreg[i][j + 0];
                float xv1 = vreg[i][j + 1];
                float xv2 = vreg[i][j + 2];
                float xv3 = vreg[i][j + 3];
                SEG(iv.x, nq.x, dv.x);
                SEG(iv.y, nq.y, dv.y);
                SEG(iv.z, nq.z, dv.z);
                SEG(iv.w, nq.w, dv.w);
            }
        }
    }
#undef SEG
#undef FILL

    // ---- Phase 2: reduce across the 8 warps ----
    const int g = rl * 8 + (lane & 7);     // 0..31 pixel group within strip
    s_red[warp][g] = make_float4(acc0, acc1, acc2, acc3);
    __syncthreads();

    if (tid < 32) {
        float bias = s_bias;
        float4 r0 = s_red[0][tid];
        float4 r1 = s_red[1][tid];
        float4 r2 = s_red[2][tid];
        float4 r3 = s_red[3][tid];
        float4 r4 = s_red[4][tid];
        float4 r5 = s_red[5][tid];
        float4 r6 = s_red[6][tid];
        float4 r7 = s_red[7][tid];
        float4 res;
        res.x = bias + ((r0.x + r1.x) + (r2.x + r3.x)) + ((r4.x + r5.x) + (r6.x + r7.x));
        res.y = bias + ((r0.y + r1.y) + (r2.y + r3.y)) + ((r4.y + r5.y) + (r6.y + r7.y));
        res.z = bias + ((r0.z + r1.z) + (r2.z + r3.z)) + ((r4.z + r5.z) + (r6.z + r7.z));
        res.w = bias + ((r0.w + r1.w) + (r2.w + r3.w)) + ((r4.w + r5.w) + (r6.w + r7.w));
        int row = tid >> 3;
        int col0 = (tid & 7) * 4;
        int oidx = ((b * O_ + o) * HW_ + y0 + row) * HW_ + col0;
        *reinterpret_cast<float4*>(out + oidx) = res;
    }
}

extern "C" void kernel_launch(void* const* d_in, const int* in_sizes, int n_in,
                              void* d_out, int out_size) {
    const float* x   = (const float*)d_in[0];
    const float* pos = (const float*)d_in[1];
    const float* val = (const float*)d_in[2];
    float* out = (float*)d_out;

    pc_fused<<<B_ * O_ * 8, 256>>>(x, pos, val, out);
}

// round 10
// speedup vs baseline: 1.1969x; 1.0082x over previous
#include <cuda_runtime.h>

#define B_  4
#define O_  32
#define C_  32
#define HW_ 32
#define P_  5
#define T_  (C_ * 9)      // 288 taps per output channel
#define EPSF 1e-6f
#define TS_ 36            // x-tile row stride (floats), rows 16B-aligned

// fused multiply-add with saturate-to-[0,1] — proven exact vs reference
__device__ __forceinline__ float fma_sat(float a, float b, float c) {
    float d;
    asm("fma.rn.sat.f32 %0, %1, %2, %3;" : "=f"(d) : "f"(a), "f"(b), "f"(c));
    return d;
}

// ---------------------------------------------------------------------------
// Grid: 1024 = (b, o, 4-row strip of 8). Block: 256 = 8 warps,
// __launch_bounds__(256,5): <=48 regs -> 5 resident blocks/SM (40 warps) to
// close the fma-pipe feed gap (R9: fma stream needs 78% of cycles but only
// 42% occupancy left 22% of them empty).
// Phase 0: per-block sort of this o's 288 (pos,val)[5] tables ->
//   f(x) = v0 + sum_k dv_k * sat((x-p_k)*inv_k)   [exact vs reference]
//   3 float4 per tap -> 3 uniform LDS.128 broadcasts.
// Phase 1: warp w: channels 4w..4w+3, 4 px/thread; per-warp double-buffered
//   6x36 x-tile; ROLLING row loads (6 floats live instead of 18).
// Phase 2: 8-way float4 smem reduction + bias, STG.128.
// ---------------------------------------------------------------------------
__global__ __launch_bounds__(256, 5) void pc_fused(const float* __restrict__ x,
                                                   const float* __restrict__ pos,
                                                   const float* __restrict__ val,
                                                   float* __restrict__ out) {
    const int blk = blockIdx.x;
    const int strip = blk & 7;             // 0..7 : 4-row strip
    const int o = (blk >> 3) & 31;
    const int b = blk >> 8;
    const int y0 = strip * 4;

    __shared__ float4 s_tab[T_ * 3];        // 13824 B
    __shared__ float  s_v0[T_];             // 1152 B
    __shared__ float  s_x[16][6 * TS_];     // 2 tiles/warp, 13824 B
    __shared__ float4 s_red[8][32];         // 4096 B
    __shared__ float  s_bias;

    const int tid = threadIdx.x;

    // ---- Phase 0: build coefficient tables for this o ----
    const float* pbase = pos + o * (T_ * P_);
    const float* vbase = val + o * (T_ * P_);
#pragma unroll
    for (int rep = 0; rep < 2; rep++) {
        int ot = tid + rep * 256;
        if (ot < T_) {
            float p[P_], v[P_];
#pragma unroll
            for (int k = 0; k < P_; k++) { p[k] = pbase[ot * P_ + k]; v[k] = vbase[ot * P_ + k]; }
#define CE(a, bb) do { if (p[a] > p[bb]) { float t0 = p[a]; p[a] = p[bb]; p[bb] = t0; \
                                           float t1 = v[a]; v[a] = v[bb]; v[bb] = t1; } } while (0)
            CE(0,1); CE(3,4); CE(2,4); CE(2,3); CE(1,4); CE(0,3); CE(0,2); CE(1,3); CE(1,2);
#undef CE
            float inv[4], nq[4], dv[4];
#pragma unroll
            for (int k = 0; k < 4; k++) {
                float den = p[k + 1] - p[k] + EPSF;
                inv[k] = 1.0f / den;
                nq[k]  = -p[k] * inv[k];
                dv[k]  = v[k + 1] - v[k];
            }
            s_tab[ot * 3 + 0] = make_float4(inv[0], inv[1], inv[2], inv[3]);
            s_tab[ot * 3 + 1] = make_float4(nq[0],  nq[1],  nq[2],  nq[3]);
            s_tab[ot * 3 + 2] = make_float4(dv[0],  dv[1],  dv[2],  dv[3]);
            s_v0[ot] = v[0];
        }
    }
    __syncthreads();

    if (tid < 32) {        // bias = sum_t v0
        float s = 0.0f;
#pragma unroll
        for (int k = 0; k < 9; k++) s += s_v0[tid + k * 32];
#pragma unroll
        for (int off = 16; off > 0; off >>= 1) s += __shfl_down_sync(0xffffffffu, s, off);
        if (tid == 0) s_bias = s;
    }
    __syncthreads();

    // ---- Phase 1 ----
    const int warp = tid >> 5;
    const int lane = tid & 31;
    const int rl   = lane >> 3;            // 0..3: row within strip
    const int xg   = (lane & 7) * 4;       // 0,4,...,28
    const int rowbase = y0 - 1;            // tile row 0 = global row y0-1

    float acc0 = 0.0f, acc1 = 0.0f, acc2 = 0.0f, acc3 = 0.0f;

    const float* xb = x + b * (C_ * HW_ * HW_);
    const int cBase = warp * 4;            // 4 channels per warp
    const float* xc = xb + cBase * (HW_ * HW_);
    float* tA = s_x[warp * 2];
    float* tB = s_x[warp * 2 + 1];

// Fill one 6x34 tile; bounds predicates recomputed inline (saves ~15 regs).
#define FILL(T_PTR, XC) do {                                               \
    const float* xp_ = (XC);                                               \
    _Pragma("unroll")                                                      \
    for (int rr = 0; rr < 6; rr++) {                                       \
        int gy_ = rowbase + rr;                                            \
        bool rowok_ = (gy_ >= 0) && (gy_ < HW_);                           \
        float v_ = (rowok_ && lane >= 1) ? xp_[gy_ * HW_ + lane - 1] : 0.0f; \
        (T_PTR)[rr * TS_ + lane] = v_;                                     \
        if (lane < 2) {                                                    \
            float v2_ = (rowok_ && lane == 0) ? xp_[gy_ * HW_ + 31] : 0.0f; \
            (T_PTR)[rr * TS_ + 32 + lane] = v2_;                           \
        }                                                                  \
    } } while (0)

// One segment for all 4 pixels: FFMA.SAT + FFMA each
#define SEG(CI, CQ, CD) do {                                               \
        float u0 = fma_sat(rrow[jj + 0], (CI), (CQ));                      \
        float u1 = fma_sat(rrow[jj + 1], (CI), (CQ));                      \
        float u2 = fma_sat(rrow[jj + 2], (CI), (CQ));                      \
        float u3 = fma_sat(rrow[jj + 3], (CI), (CQ));                      \
        acc0 = fmaf(u0, (CD), acc0);                                       \
        acc1 = fmaf(u1, (CD), acc1);                                       \
        acc2 = fmaf(u2, (CD), acc2);                                       \
        acc3 = fmaf(u3, (CD), acc3);                                       \
    } while (0)

    FILL(tA, xc);                          // prefetch first channel

    for (int cc = 0; cc < 4; cc++) {
        float* cur = (cc & 1) ? tB : tA;
        float* nxt = (cc & 1) ? tA : tB;
        __syncwarp();                      // tile ready / prev reads done

        if (cc < 3) FILL(nxt, xc + (HW_ * HW_));   // LDG overlaps whole tap block
        xc += HW_ * HW_;

        const float4* tp = s_tab + (cBase + cc) * 27;
#pragma unroll
        for (int i = 0; i < 3; i++) {
            // rolling 6-wide row load: LDS.128 + LDS.64 (rows 16B-aligned)
            float rrow[6];
            {
                const float* rp = cur + (rl + i) * TS_ + xg;
                float4 a = *reinterpret_cast<const float4*>(rp);
                float2 bb = *reinterpret_cast<const float2*>(rp + 4);
                rrow[0] = a.x; rrow[1] = a.y; rrow[2] = a.z;
                rrow[3] = a.w; rrow[4] = bb.x; rrow[5] = bb.y;
            }
#pragma unroll
            for (int jj = 0; jj < 3; jj++) {
                float4 iv = tp[(i * 3 + jj) * 3 + 0];   // uniform -> broadcast
                float4 nq = tp[(i * 3 + jj) * 3 + 1];
                float4 dv = tp[(i * 3 + jj) * 3 + 2];
                SEG(iv.x, nq.x, dv.x);
                SEG(iv.y, nq.y, dv.y);
                SEG(iv.z, nq.z, dv.z);
                SEG(iv.w, nq.w, dv.w);
            }
        }
    }
#undef SEG
#undef FILL

    // ---- Phase 2: reduce across the 8 warps ----
    const int g = rl * 8 + (lane & 7);     // 0..31 pixel group within strip
    s_red[warp][g] = make_float4(acc0, acc1, acc2, acc3);
    __syncthreads();

    if (tid < 32) {
        float bias = s_bias;
        float4 r0 = s_red[0][tid];
        float4 r1 = s_red[1][tid];
        float4 r2 = s_red[2][tid];
        float4 r3 = s_red[3][tid];
        float4 r4 = s_red[4][tid];
        float4 r5 = s_red[5][tid];
        float4 r6 = s_red[6][tid];
        float4 r7 = s_red[7][tid];
        float4 res;
        res.x = bias + ((r0.x + r1.x) + (r2.x + r3.x)) + ((r4.x + r5.x) + (r6.x + r7.x));
        res.y = bias + ((r0.y + r1.y) + (r2.y + r3.y)) + ((r4.y + r5.y) + (r6.y + r7.y));
        res.z = bias + ((r0.z + r1.z) + (r2.z + r3.z)) + ((r4.z + r5.z) + (r6.z + r7.z));
        res.w = bias + ((r0.w + r1.w) + (r2.w + r3.w)) + ((r4.w + r5.w) + (r6.w + r7.w));
        int row = tid >> 3;
        int col0 = (tid & 7) * 4;
        int oidx = ((b * O_ + o) * HW_ + y0 + row) * HW_ + col0;
        *reinterpret_cast<float4*>(out + oidx) = res;
    }
}

extern "C" void kernel_launch(void* const* d_in, const int* in_sizes, int n_in,
                              void* d_out, int out_size) {
    const float* x   = (const float*)d_in[0];
    const float* pos = (const float*)d_in[1];
    const float* val = (const float*)d_in[2];
    float* out = (float*)d_out;

    pc_fused<<<B_ * O_ * 8, 256>>>(x, pos, val, out);
}

// round 12
// speedup vs baseline: 1.2685x; 1.0598x over previous
#include <cuda_runtime.h>

#define B_  4
#define O_  32
#define C_  32
#define HW_ 32
#define P_  5
#define T_  (C_ * 9)      // 288 taps per output channel
#define EPSF 1e-6f
#define TSP_ 36           // pair-row stride in u64 (rows 16B-aligned)

typedef unsigned long long u64;

__device__ __forceinline__ u64 pk(float lo, float hi) {
    u64 r; asm("mov.b64 %0, {%1, %2};" : "=l"(r) : "f"(lo), "f"(hi)); return r;
}
__device__ __forceinline__ void upk(float& lo, float& hi, u64 v) {
    asm("mov.b64 {%0, %1}, %2;" : "=f"(lo), "=f"(hi) : "l"(v));
}
__device__ __forceinline__ u64 fma2(u64 a, u64 b, u64 c) {
    u64 d; asm("fma.rn.f32x2 %0, %1, %2, %3;" : "=l"(d) : "l"(a), "l"(b), "l"(c));
    return d;
}
__device__ __forceinline__ u64 add2(u64 a, u64 b) {
    u64 d; asm("add.rn.f32x2 %0, %1, %2;" : "=l"(d) : "l"(a), "l"(b));
    return d;
}
// Per-half saturate of a packed pair via rt-1 immediate-form FFMA.SAT.
// Single asm block: mov.b64 unpack/pack lets ptxas alias the halves onto the
// register pairs (no MOVs in the good case). sat(rn(u)) == clamp to [0,1],
// identical to the validated unfused-clamp numerics.
__device__ __forceinline__ u64 sat2(u64 u) {
    u64 s;
    asm("{\n\t"
        ".reg .f32 lo, hi;\n\t"
        "mov.b64 {lo, hi}, %1;\n\t"
        "fma.rn.sat.f32 lo, lo, 0f3F800000, 0f00000000;\n\t"
        "fma.rn.sat.f32 hi, hi, 0f3F800000, 0f00000000;\n\t"
        "mov.b64 %0, {lo, hi};\n\t"
        "}" : "=l"(s) : "l"(u));
    return s;
}

// ---------------------------------------------------------------------------
// Packed-pair kernel: pixels paired VERTICALLY at stride 4 (rows r and r+4 of
// an 8-row strip) so every operand is natively u64 — x pairs pre-packed in
// shared, coefficients pre-duplicated, accumulators packed. No repack MOVs.
// Math per 2px-seg: FFMA2 (ramp) + 2x rt-1 FFMA.SAT-imm (clamp) + FFMA2 (acc)
// = 6 fma-pipe cycles / 4 issue slots per 2 pixels (vs 8/4 scalar).
// Grid: 512 = (b, o, 8-row strip). Block: 256 = 8 warps; warp w = channels
// 4w..4w+3 over the strip, 8 px/thread (4 vertical pairs) -> FILL overhead
// per pixel halved vs the 4 px/thread scalar kernel.
// ---------------------------------------------------------------------------
__global__ __launch_bounds__(256, 4) void pc_fused(const float* __restrict__ x,
                                                   const float* __restrict__ pos,
                                                   const float* __restrict__ val,
                                                   float* __restrict__ out) {
    const int blk = blockIdx.x;
    const int quarter = blk & 3;           // 8-row strip
    const int o = (blk >> 2) & 31;
    const int b = blk >> 7;
    const int y0 = quarter * 8;

    __shared__ ulonglong2 s_tab[T_ * 6];            // 27648 B (u64-dup coeffs)
    __shared__ float      s_v0[T_];                 // 1152 B
    __shared__ __align__(16) u64 s_x[8][6 * TSP_];  // 13824 B (packed tiles)
    __shared__ float      s_bias;
    // reduction area aliases s_x after a __syncthreads (8*32*4 u64 = 8192 B)
    u64* red = &s_x[0][0];

    const int tid = threadIdx.x;

    // ---- Phase 0: sort + duplicated coefficient tables ----
    const float* pbase = pos + o * (T_ * P_);
    const float* vbase = val + o * (T_ * P_);
#pragma unroll
    for (int rep = 0; rep < 2; rep++) {
        int ot = tid + rep * 256;
        if (ot < T_) {
            float p[P_], v[P_];
#pragma unroll
            for (int k = 0; k < P_; k++) { p[k] = pbase[ot * P_ + k]; v[k] = vbase[ot * P_ + k]; }
#define CE(a, bb) do { if (p[a] > p[bb]) { float t0 = p[a]; p[a] = p[bb]; p[bb] = t0; \
                                           float t1 = v[a]; v[a] = v[bb]; v[bb] = t1; } } while (0)
            CE(0,1); CE(3,4); CE(2,4); CE(2,3); CE(1,4); CE(0,3); CE(0,2); CE(1,3); CE(1,2);
#undef CE
            float* tf = (float*)(s_tab + ot * 6);   // 24 floats per tap
#pragma unroll
            for (int k = 0; k < 4; k++) {
                float den = p[k + 1] - p[k] + EPSF;
                float inv = 1.0f / den;
                float nq  = -p[k] * inv;
                float dv  = v[k + 1] - v[k];
                tf[4 * k + 0] = inv; tf[4 * k + 1] = inv;
                tf[4 * k + 2] = nq;  tf[4 * k + 3] = nq;
                tf[16 + 2 * k + 0] = dv; tf[16 + 2 * k + 1] = dv;
            }
            s_v0[ot] = v[0];
        }
    }
    __syncthreads();

    if (tid < 32) {        // bias = sum_t v0
        float s = 0.0f;
#pragma unroll
        for (int k = 0; k < 9; k++) s += s_v0[tid + k * 32];
#pragma unroll
        for (int off = 16; off > 0; off >>= 1) s += __shfl_down_sync(0xffffffffu, s, off);
        if (tid == 0) s_bias = s;
    }
    __syncthreads();

    // ---- Phase 1 ----
    const int warp = tid >> 5;
    const int lane = tid & 31;
    const int rl   = lane >> 3;            // 0..3: pair row group (rows rl, rl+4)
    const int xg   = (lane & 7) * 4;       // 0,4,...,28

    u64 acc0 = 0ull, acc1 = 0ull, acc2 = 0ull, acc3 = 0ull;

    const float* xb = x + b * (C_ * HW_ * HW_);
    const int cBase = warp * 4;            // 4 channels per warp
    const float* xc = xb + cBase * (HW_ * HW_);
    u64* tile = s_x[warp];

// Fill packed tile: pair-row k holds (x[y0+k-1], x[y0+k+3]) at col scol-1.
#define FILL(XC) do {                                                      \
    const float* xp_ = (XC);                                               \
    _Pragma("unroll")                                                      \
    for (int k = 0; k < 6; k++) {                                          \
        int gyL_ = y0 + k - 1;                                             \
        int gyH_ = y0 + k + 3;                                             \
        int gx_ = lane - 1;                                                \
        bool cok_ = (gx_ >= 0);                                            \
        float lo_ = (cok_ && gyL_ >= 0 && gyL_ < HW_) ? xp_[gyL_ * HW_ + gx_] : 0.0f; \
        float hi_ = (cok_ && gyH_ < HW_) ? xp_[gyH_ * HW_ + gx_] : 0.0f;   \
        tile[k * TSP_ + lane] = pk(lo_, hi_);                              \
        if (lane < 2) {                                                    \
            int gx2_ = 31 + lane;                                          \
            bool c2_ = (gx2_ < HW_);                                       \
            float lo2_ = (c2_ && gyL_ >= 0 && gyL_ < HW_) ? xp_[gyL_ * HW_ + gx2_] : 0.0f; \
            float hi2_ = (c2_ && gyH_ < HW_) ? xp_[gyH_ * HW_ + gx2_] : 0.0f; \
            tile[k * TSP_ + 32 + lane] = pk(lo2_, hi2_);                   \
        }                                                                  \
    } } while (0)

// One segment, 4 pixel-pairs: FFMA2 + sat2 + FFMA2 each.
#define SEG(IV2, NQ2, DV2) do {                                            \
        u64 u0 = fma2(xp[jj + 0], (IV2), (NQ2));                           \
        u64 u1 = fma2(xp[jj + 1], (IV2), (NQ2));                           \
        u64 u2 = fma2(xp[jj + 2], (IV2), (NQ2));                           \
        u64 u3 = fma2(xp[jj + 3], (IV2), (NQ2));                           \
        u0 = sat2(u0);                                                     \
        u1 = sat2(u1);                                                     \
        u2 = sat2(u2);                                                     \
        u3 = sat2(u3);                                                     \
        acc0 = fma2(u0, (DV2), acc0);                                      \
        acc1 = fma2(u1, (DV2), acc1);                                      \
        acc2 = fma2(u2, (DV2), acc2);                                      \
        acc3 = fma2(u3, (DV2), acc3);                                      \
    } while (0)

    for (int cc = 0; cc < 4; cc++) {
        __syncwarp();                      // prev reads done before overwrite
        FILL(xc);
        xc += HW_ * HW_;
        __syncwarp();                      // tile visible

        const ulonglong2* tp = s_tab + (cBase + cc) * 9 * 6;
#pragma unroll
        for (int i = 0; i < 3; i++) {
            // 6 x-pairs for this tap row: 3 x LDS.128 (16B-aligned)
            u64 xp[6];
            {
                const ulonglong2* rp =
                    reinterpret_cast<const ulonglong2*>(tile + (rl + i) * TSP_ + xg);
                ulonglong2 a = rp[0], bq = rp[1], cq = rp[2];
                xp[0] = a.x;  xp[1] = a.y;
                xp[2] = bq.x; xp[3] = bq.y;
                xp[4] = cq.x; xp[5] = cq.y;
            }
#pragma unroll
            for (int jj = 0; jj < 3; jj++) {
                const ulonglong2* t6 = tp + (i * 3 + jj) * 6;
                ulonglong2 c0 = t6[0];     // {(inv0,inv0),(nq0,nq0)} broadcast
                ulonglong2 c1 = t6[1];
                ulonglong2 c2 = t6[2];
                ulonglong2 c3 = t6[3];
                ulonglong2 d01 = t6[4];    // {(dv0,dv0),(dv1,dv1)}
                ulonglong2 d23 = t6[5];    // {(dv2,dv2),(dv3,dv3)}
                SEG(c0.x, c0.y, d01.x);
                SEG(c1.x, c1.y, d01.y);
                SEG(c2.x, c2.y, d23.x);
                SEG(c3.x, c3.y, d23.y);
            }
        }
    }
#undef SEG
#undef FILL

    // ---- Phase 2: reduce across the 8 warps (red aliases s_x) ----
    __syncthreads();                       // all tile reads done
    red[(warp * 32 + lane) * 4 + 0] = acc0;
    red[(warp * 32 + lane) * 4 + 1] = acc1;
    red[(warp * 32 + lane) * 4 + 2] = acc2;
    red[(warp * 32 + lane) * 4 + 3] = acc3;
    __syncthreads();

    if (tid < 32) {
        u64 r0 = 0ull, r1 = 0ull, r2 = 0ull, r3 = 0ull;
#pragma unroll
        for (int w = 0; w < 8; w++) {
            const ulonglong2* q = reinterpret_cast<const ulonglong2*>(red + (w * 32 + tid) * 4);
            ulonglong2 qa = q[0], qb = q[1];
            r0 = add2(r0, qa.x); r1 = add2(r1, qa.y);
            r2 = add2(r2, qb.x); r3 = add2(r3, qb.y);
        }
        float bias = s_bias;
        u64 bias2 = pk(bias, bias);
        r0 = add2(r0, bias2); r1 = add2(r1, bias2);
        r2 = add2(r2, bias2); r3 = add2(r3, bias2);
        float l0, h0, l1, h1, l2, h2, l3, h3;
        upk(l0, h0, r0); upk(l1, h1, r1); upk(l2, h2, r2); upk(l3, h3, r3);
        int rlo = tid >> 3;
        int col0 = (tid & 7) * 4;
        int base = ((b * O_ + o) * HW_ + y0) * HW_;
        *reinterpret_cast<float4*>(out + base + rlo * HW_ + col0) =
            make_float4(l0, l1, l2, l3);
        *reinterpret_cast<float4*>(out + base + (rlo + 4) * HW_ + col0) =
            make_float4(h0, h1, h2, h3);
    }
}

extern "C" void kernel_launch(void* const* d_in, const int* in_sizes, int n_in,
                              void* d_out, int out_size) {
    const float* x   = (const float*)d_in[0];
    const float* pos = (const float*)d_in[1];
    const float* val = (const float*)d_in[2];
    float* out = (float*)d_out;

    pc_fused<<<B_ * O_ * 4, 256>>>(x, pos, val, out);
}